// round 11
// baseline (speedup 1.0000x reference)
#include <cuda_runtime.h>
#include <cuda_bf16.h>
#include <cstdint>

// Problem constants
#define BATCH 16
#define CDIM  256
#define NPix  4096
#define HEADS 4
#define DH    64
#define O3    768
#define NSPLIT 16

// Scratch (__device__ globals: allocation-free rule)
__device__ __nv_bfloat16 g_qkv[(size_t)BATCH * O3 * NPix];     // K,V live in rows [256,768)
__device__ __nv_bfloat16 g_xb [(size_t)BATCH * CDIM * NPix];   // 33 MB
__device__ __nv_bfloat16 g_wq [(size_t)O3 * CDIM];             // 384 KB
__device__ float g_ctxp[(size_t)NSPLIT * BATCH * HEADS * DH * DH]; // 16 MB
__device__ float g_zp  [(size_t)NSPLIT * BATCH * HEADS * DH];      // 256 KB
__device__ __nv_bfloat16 g_M [(size_t)BATCH * CDIM * CDIM];    // 2 MB
__device__ __nv_bfloat16 g_Mq[(size_t)BATCH * CDIM * CDIM];    // 2 MB  (M @ W_q)

__device__ __forceinline__ uint32_t cvta_s(const void* p) {
    return (uint32_t)__cvta_generic_to_shared(p);
}
__device__ __forceinline__ void cp16(uint32_t dst, const void* src) {
    asm volatile("cp.async.cg.shared.global [%0], [%1], 16;" :: "r"(dst), "l"(src));
}
#define CP_COMMIT() asm volatile("cp.async.commit_group;")
#define CP_WAIT(n)  asm volatile("cp.async.wait_group %0;" :: "n"(n))

#define LDSM_X4(r0,r1,r2,r3,addr) \
    asm volatile("ldmatrix.sync.aligned.m8n8.x4.shared.b16 {%0,%1,%2,%3}, [%4];" \
                 : "=r"(r0),"=r"(r1),"=r"(r2),"=r"(r3) : "r"(addr))
#define LDSM_X4_T(r0,r1,r2,r3,addr) \
    asm volatile("ldmatrix.sync.aligned.m8n8.x4.trans.shared.b16 {%0,%1,%2,%3}, [%4];" \
                 : "=r"(r0),"=r"(r1),"=r"(r2),"=r"(r3) : "r"(addr))
#define MMA_BF16(c,a,b0,b1) \
    asm volatile("mma.sync.aligned.m16n8k16.row.col.f32.bf16.bf16.f32 " \
                 "{%0,%1,%2,%3},{%4,%5,%6,%7},{%8,%9},{%0,%1,%2,%3};" \
                 : "+f"((c)[0]),"+f"((c)[1]),"+f"((c)[2]),"+f"((c)[3]) \
                 : "r"((a)[0]),"r"((a)[1]),"r"((a)[2]),"r"((a)[3]),"r"(b0),"r"(b1))

// ---------------------------------------------------------------------------
// Conversion kernels (fp32 -> bf16)
// ---------------------------------------------------------------------------
__global__ __launch_bounds__(256) void k_cvt_x(const float* __restrict__ x) {
    size_t i = ((size_t)blockIdx.x * 256 + threadIdx.x) * 4;
    float4 v = *(const float4*)&x[i];
    __nv_bfloat162 lo, hi;
    lo.x = __float2bfloat16_rn(v.x); lo.y = __float2bfloat16_rn(v.y);
    hi.x = __float2bfloat16_rn(v.z); hi.y = __float2bfloat16_rn(v.w);
    *(__nv_bfloat162*)&g_xb[i]     = lo;
    *(__nv_bfloat162*)&g_xb[i + 2] = hi;
}
__global__ __launch_bounds__(256) void k_cvt_w(const float* __restrict__ w) {
    size_t i = ((size_t)blockIdx.x * 256 + threadIdx.x) * 4;
    float4 v = *(const float4*)&w[i];
    __nv_bfloat162 lo, hi;
    lo.x = __float2bfloat16_rn(v.x); lo.y = __float2bfloat16_rn(v.y);
    hi.x = __float2bfloat16_rn(v.z); hi.y = __float2bfloat16_rn(v.w);
    *(__nv_bfloat162*)&g_wq[i]     = lo;
    *(__nv_bfloat162*)&g_wq[i + 2] = hi;
}

// ---------------------------------------------------------------------------
// Kernel 1: K,V only. qkv[b,o,n] = sum_c W[o,c]*x[b,c,n], o in [256,768)
// bf16 HMMA, 128x128x32 tiles, cp.async double-buffered, 1 sync/iter
// ---------------------------------------------------------------------------
__global__ __launch_bounds__(256, 2) void k_qkv() {
    __shared__ __nv_bfloat16 As[2][128][40];    // [o][c]
    __shared__ __nv_bfloat16 Bs[2][32][136];    // [c][n]

    const int b  = blockIdx.z;
    const int o0 = CDIM + blockIdx.y * 128;     // skip Q rows
    const int n0 = blockIdx.x * 128;
    const __nv_bfloat16* Xb = g_xb + (size_t)b * CDIM * NPix;
    __nv_bfloat16*       Cb = g_qkv + (size_t)b * O3 * NPix;

    const int tid  = threadIdx.x;
    const int lane = tid & 31;
    const int wid  = tid >> 5;
    const int wm0  = (wid & 3) * 32;
    const int wn0  = (wid >> 2) * 64;

    const int aR0 = tid >> 2,          aC0 = (tid & 3) * 8;
    const int aR1 = (tid + 256) >> 2,  aC1 = ((tid + 256) & 3) * 8;
    const int bR0 = tid >> 4,          bC0 = (tid & 15) * 8;
    const int bR1 = (tid + 256) >> 4,  bC1 = ((tid + 256) & 15) * 8;
    const __nv_bfloat16* aS0 = &g_wq[(size_t)(o0 + aR0) * CDIM + aC0];
    const __nv_bfloat16* aS1 = &g_wq[(size_t)(o0 + aR1) * CDIM + aC1];
    const __nv_bfloat16* bS0 = &Xb[(size_t)bR0 * NPix + n0 + bC0];
    const __nv_bfloat16* bS1 = &Xb[(size_t)bR1 * NPix + n0 + bC1];

    auto stage = [&](int buf, int c0) {
        cp16(cvta_s(&As[buf][aR0][aC0]), aS0 + c0);
        cp16(cvta_s(&As[buf][aR1][aC1]), aS1 + c0);
        cp16(cvta_s(&Bs[buf][bR0][bC0]), bS0 + (size_t)c0 * NPix);
        cp16(cvta_s(&Bs[buf][bR1][bC1]), bS1 + (size_t)c0 * NPix);
    };

    float acc[2][8][4] = {};

    stage(0, 0);
    CP_COMMIT();

    #pragma unroll
    for (int it = 0; it < 8; it++) {          // CDIM/32 = 8 k-steps
        const int buf = it & 1;
        CP_WAIT(0);
        __syncthreads();
        if (it < 7) { stage(buf ^ 1, (it + 1) * 32); CP_COMMIT(); }

        #pragma unroll
        for (int kk = 0; kk < 32; kk += 16) {
            uint32_t a[2][4];
            #pragma unroll
            for (int mi = 0; mi < 2; mi++) {
                uint32_t ad = cvta_s(&As[buf][wm0 + mi * 16 + (lane & 15)][kk + (lane >> 4) * 8]);
                LDSM_X4(a[mi][0], a[mi][1], a[mi][2], a[mi][3], ad);
            }
            uint32_t bfr[8][2];
            #pragma unroll
            for (int np = 0; np < 4; np++) {
                uint32_t ad = cvta_s(&Bs[buf][kk + ((lane >> 3) & 1) * 8 + (lane & 7)]
                                            [wn0 + np * 16 + (lane >> 4) * 8]);
                uint32_t r0, r1, r2, r3;
                LDSM_X4_T(r0, r1, r2, r3, ad);
                bfr[2*np][0] = r0; bfr[2*np][1] = r1;
                bfr[2*np+1][0] = r2; bfr[2*np+1][1] = r3;
            }
            #pragma unroll
            for (int mi = 0; mi < 2; mi++)
                #pragma unroll
                for (int ni = 0; ni < 8; ni++)
                    MMA_BF16(acc[mi][ni], a[mi], bfr[ni][0], bfr[ni][1]);
        }
    }

    #pragma unroll
    for (int mi = 0; mi < 2; mi++) {
        int r0 = o0 + wm0 + mi * 16 + (lane >> 2);
        #pragma unroll
        for (int ni = 0; ni < 8; ni++) {
            int cc = n0 + wn0 + ni * 8 + (lane & 3) * 2;
            __nv_bfloat162 v0, v1;
            v0.x = __float2bfloat16_rn(acc[mi][ni][0]);
            v0.y = __float2bfloat16_rn(acc[mi][ni][1]);
            v1.x = __float2bfloat16_rn(acc[mi][ni][2]);
            v1.y = __float2bfloat16_rn(acc[mi][ni][3]);
            *(__nv_bfloat162*)&Cb[(size_t)r0 * NPix + cc]       = v0;
            *(__nv_bfloat162*)&Cb[(size_t)(r0 + 8) * NPix + cc] = v1;
        }
    }
}

// ---------------------------------------------------------------------------
// Kernel 2: partial unnormalized context + partial Z.
//   ctxp[s][bh][d][e] = sum_{n in split} exp(k[d,n]) * v[e,n]
//   zp[s][bh][d]      = sum_{n in split} exp(k[d,n])
// NSPLIT=16 (256 n per block, 4 chunks of 64). K: register LDG + exp.
// V: cp.async (no transform). Double-buffered smem, 1 sync/iter.
// ---------------------------------------------------------------------------
__global__ __launch_bounds__(256) void k_ctx() {
    const int split = blockIdx.x;
    const int bh = blockIdx.y;
    const int b = bh >> 2;
    const int h = bh & 3;
    const __nv_bfloat16* kp = g_qkv + (size_t)b * O3 * NPix + (size_t)(CDIM + h * DH) * NPix;
    const __nv_bfloat16* vp = g_qkv + (size_t)b * O3 * NPix + (size_t)(2 * CDIM + h * DH) * NPix;

    __shared__ __nv_bfloat16 Ks[2][64][72];
    __shared__ __nv_bfloat16 Vs[2][64][72];

    const int tid  = threadIdx.x;
    const int lane = tid & 31;
    const int wid  = tid >> 5;
    const int wm0  = (wid & 3) * 16;   // d
    const int wn0  = (wid >> 2) * 32;  // e

    const int srow = tid >> 2;         // staging row, 0..63
    const int scol = (tid & 3) * 16;   // staging col base (16 bf16 per thread)

    const __nv_bfloat16* kSrc = &kp[(size_t)srow * NPix + scol];
    const __nv_bfloat16* vSrc = &vp[(size_t)srow * NPix + scol];

    float acc[4][4] = {};
    float zacc = 0.f;
    const int nbeg = split * (NPix / NSPLIT);   // 256-wide slice

    // Prologue: K regs + V cp.async for chunk 0
    uint4 kr0 = *(const uint4*)(kSrc + nbeg);
    uint4 kr1 = *(const uint4*)(kSrc + nbeg + 8);
    cp16(cvta_s(&Vs[0][srow][scol]),     vSrc + nbeg);
    cp16(cvta_s(&Vs[0][srow][scol + 8]), vSrc + nbeg + 8);
    CP_COMMIT();

    #pragma unroll
    for (int it = 0; it < 4; it++) {        // 256/64 = 4 chunks per split
        const int buf = it & 1;
        {   // exp(K) -> smem
            __nv_bfloat162 ko[8];
            const __nv_bfloat162* ka = (const __nv_bfloat162*)&kr0;
            const __nv_bfloat162* kb = (const __nv_bfloat162*)&kr1;
            #pragma unroll
            for (int j = 0; j < 4; j++) {
                float2 f = __bfloat1622float2(ka[j]);
                float e0 = __expf(f.x), e1 = __expf(f.y);
                zacc += e0 + e1;
                ko[j].x = __float2bfloat16_rn(e0);
                ko[j].y = __float2bfloat16_rn(e1);
            }
            #pragma unroll
            for (int j = 0; j < 4; j++) {
                float2 f = __bfloat1622float2(kb[j]);
                float e0 = __expf(f.x), e1 = __expf(f.y);
                zacc += e0 + e1;
                ko[4 + j].x = __float2bfloat16_rn(e0);
                ko[4 + j].y = __float2bfloat16_rn(e1);
            }
            *(uint4*)&Ks[buf][srow][scol]     = *(uint4*)&ko[0];
            *(uint4*)&Ks[buf][srow][scol + 8] = *(uint4*)&ko[4];
        }
        CP_WAIT(0);
        __syncthreads();   // covers V arrival + K STS visibility + prior MMA reads

        if (it < 3) {       // prefetch next chunk; latency hides under MMA
            const int nn = nbeg + (it + 1) * 64;
            kr0 = *(const uint4*)(kSrc + nn);
            kr1 = *(const uint4*)(kSrc + nn + 8);
            cp16(cvta_s(&Vs[buf ^ 1][srow][scol]),     vSrc + nn);
            cp16(cvta_s(&Vs[buf ^ 1][srow][scol + 8]), vSrc + nn + 8);
            CP_COMMIT();
        }

        #pragma unroll
        for (int kk = 0; kk < 64; kk += 16) {
            uint32_t a[4];
            {
                uint32_t ad = cvta_s(&Ks[buf][wm0 + (lane & 15)][kk + (lane >> 4) * 8]);
                LDSM_X4(a[0], a[1], a[2], a[3], ad);
            }
            uint32_t bfr[4][2];
            #pragma unroll
            for (int np = 0; np < 2; np++) {
                int g = lane >> 3, rr = lane & 7;
                uint32_t ad = cvta_s(&Vs[buf][wn0 + np * 16 + (g >> 1) * 8 + rr][kk + (g & 1) * 8]);
                uint32_t r0, r1, r2, r3;
                LDSM_X4(r0, r1, r2, r3, ad);
                bfr[2*np][0] = r0; bfr[2*np][1] = r1;
                bfr[2*np+1][0] = r2; bfr[2*np+1][1] = r3;
            }
            #pragma unroll
            for (int ni = 0; ni < 4; ni++)
                MMA_BF16(acc[ni], a, bfr[ni][0], bfr[ni][1]);
        }
    }

    // Reduce partial Z across the 4 staging threads of each row (same warp quad)
    zacc += __shfl_xor_sync(0xffffffffu, zacc, 1);
    zacc += __shfl_xor_sync(0xffffffffu, zacc, 2);
    if ((tid & 3) == 0)
        g_zp[((size_t)split * (BATCH * HEADS) + bh) * DH + srow] = zacc;

    float* cp = g_ctxp + ((size_t)split * (BATCH * HEADS) + bh) * (DH * DH);
    #pragma unroll
    for (int ni = 0; ni < 4; ni++) {
        int d = wm0 + (lane >> 2);
        int e = wn0 + ni * 8 + (lane & 3) * 2;
        *(float2*)&cp[(size_t)d * DH + e]       = make_float2(acc[ni][0], acc[ni][1]);
        *(float2*)&cp[(size_t)(d + 8) * DH + e] = make_float2(acc[ni][2], acc[ni][3]);
    }
}

// ---------------------------------------------------------------------------
// Kernel 3: M[b][o][h*64+d] = gamma[o]/Z_d * sum_e w_out[o][h*64+e]*ctx[b,h][d][e]
// ---------------------------------------------------------------------------
__global__ __launch_bounds__(256) void k_mix(const float* __restrict__ Wout,
                                             const float* __restrict__ gamma) {
    const int bh = blockIdx.x;
    const int og = blockIdx.y;
    const int b = bh >> 2;
    const int h = bh & 3;

    __shared__ float cs[64][65];
    __shared__ float zs[64];
    const int tid = threadIdx.x;

    if (tid < 64) {
        float s = 0.f;
        #pragma unroll
        for (int sp = 0; sp < NSPLIT; sp++)
            s += g_zp[((size_t)sp * (BATCH * HEADS) + bh) * DH + tid];
        zs[tid] = 1.0f / s;
    }
    __syncthreads();

    for (int idx = tid; idx < DH * DH; idx += 256) {
        float s = 0.f;
        #pragma unroll
        for (int sp = 0; sp < NSPLIT; sp++)
            s += g_ctxp[((size_t)sp * (BATCH * HEADS) + bh) * (DH * DH) + idx];
        cs[idx >> 6][idx & 63] = s * zs[idx >> 6];
    }
    __syncthreads();

    const int o  = og * 64 + (tid >> 2);
    const int d0 = (tid & 3) * 16;

    float acc[16];
    #pragma unroll
    for (int j = 0; j < 16; j++) acc[j] = 0.f;

    for (int e = 0; e < 64; e++) {
        const float w = Wout[(size_t)o * CDIM + h * DH + e];
        #pragma unroll
        for (int j = 0; j < 16; j++)
            acc[j] = fmaf(w, cs[d0 + j][e], acc[j]);
    }
    const float g = gamma[o];
    __nv_bfloat16* mp = g_M + ((size_t)b * CDIM + o) * CDIM + h * DH + d0;
    #pragma unroll
    for (int j = 0; j < 16; j++) mp[j] = __float2bfloat16_rn(g * acc[j]);
}

// ---------------------------------------------------------------------------
// Kernel 4: Mq[b] = M[b] @ Wq   (Wq = w_qkv rows [0,256), bf16 in g_wq)
// 128x64 tiles, K=256, cp.async double-buffered, 1 sync/iter.
// ---------------------------------------------------------------------------
__global__ __launch_bounds__(256, 2) void k_mq() {
    __shared__ __nv_bfloat16 As[2][128][40];   // [o][c']
    __shared__ __nv_bfloat16 Bs[2][32][72];    // [c'][c]

    const int b  = blockIdx.z;
    const int o0 = blockIdx.y * 128;
    const int n0 = blockIdx.x * 64;
    const __nv_bfloat16* Ma = g_M  + (size_t)b * CDIM * CDIM;
    __nv_bfloat16*       Cb = g_Mq + (size_t)b * CDIM * CDIM;

    const int tid  = threadIdx.x;
    const int lane = tid & 31;
    const int wid  = tid >> 5;
    const int wm0  = (wid & 3) * 32;
    const int wn0  = (wid >> 2) * 32;

    const int aR0 = tid >> 2,          aC0 = (tid & 3) * 8;
    const int aR1 = (tid + 256) >> 2,  aC1 = ((tid + 256) & 3) * 8;
    const int bR  = tid >> 3,          bC  = (tid & 7) * 8;
    const __nv_bfloat16* aS0 = &Ma[(size_t)(o0 + aR0) * CDIM + aC0];
    const __nv_bfloat16* aS1 = &Ma[(size_t)(o0 + aR1) * CDIM + aC1];
    const __nv_bfloat16* bS  = &g_wq[(size_t)bR * CDIM + n0 + bC];

    auto stage = [&](int buf, int c0) {
        cp16(cvta_s(&As[buf][aR0][aC0]), aS0 + c0);
        cp16(cvta_s(&As[buf][aR1][aC1]), aS1 + c0);
        cp16(cvta_s(&Bs[buf][bR][bC]),   bS + (size_t)c0 * CDIM);
    };

    float acc[2][4][4] = {};

    stage(0, 0);
    CP_COMMIT();

    #pragma unroll
    for (int it = 0; it < 8; it++) {
        const int buf = it & 1;
        CP_WAIT(0);
        __syncthreads();
        if (it < 7) { stage(buf ^ 1, (it + 1) * 32); CP_COMMIT(); }

        #pragma unroll
        for (int kk = 0; kk < 32; kk += 16) {
            uint32_t a[2][4];
            #pragma unroll
            for (int mi = 0; mi < 2; mi++) {
                uint32_t ad = cvta_s(&As[buf][wm0 + mi * 16 + (lane & 15)][kk + (lane >> 4) * 8]);
                LDSM_X4(a[mi][0], a[mi][1], a[mi][2], a[mi][3], ad);
            }
            uint32_t bfr[4][2];
            #pragma unroll
            for (int np = 0; np < 2; np++) {
                uint32_t ad = cvta_s(&Bs[buf][kk + ((lane >> 3) & 1) * 8 + (lane & 7)]
                                            [wn0 + np * 16 + (lane >> 4) * 8]);
                uint32_t r0, r1, r2, r3;
                LDSM_X4_T(r0, r1, r2, r3, ad);
                bfr[2*np][0] = r0; bfr[2*np][1] = r1;
                bfr[2*np+1][0] = r2; bfr[2*np+1][1] = r3;
            }
            #pragma unroll
            for (int mi = 0; mi < 2; mi++)
                #pragma unroll
                for (int ni = 0; ni < 4; ni++)
                    MMA_BF16(acc[mi][ni], a[mi], bfr[ni][0], bfr[ni][1]);
        }
    }

    #pragma unroll
    for (int mi = 0; mi < 2; mi++) {
        int r0 = o0 + wm0 + mi * 16 + (lane >> 2);
        #pragma unroll
        for (int ni = 0; ni < 4; ni++) {
            int cc = n0 + wn0 + ni * 8 + (lane & 3) * 2;
            __nv_bfloat162 v0, v1;
            v0.x = __float2bfloat16_rn(acc[mi][ni][0]);
            v0.y = __float2bfloat16_rn(acc[mi][ni][1]);
            v1.x = __float2bfloat16_rn(acc[mi][ni][2]);
            v1.y = __float2bfloat16_rn(acc[mi][ni][3]);
            *(__nv_bfloat162*)&Cb[(size_t)r0 * CDIM + cc]       = v0;
            *(__nv_bfloat162*)&Cb[(size_t)(r0 + 8) * CDIM + cc] = v1;
        }
    }
}

// ---------------------------------------------------------------------------
// Kernel 5: y[b,o,n] = sum_c Mq[b][o][c]*xb[b,c,n] + gamma[o]*b_out[o] + x[b,o,n]
// bf16 HMMA, cp.async double-buffered, 1 sync/iter, fused fp32 epilogue
// ---------------------------------------------------------------------------
__global__ __launch_bounds__(256, 2) void k_out(const float* __restrict__ X,
                                                const float* __restrict__ b_out,
                                                const float* __restrict__ gamma,
                                                float* __restrict__ Y) {
    __shared__ __nv_bfloat16 As[2][128][40];
    __shared__ __nv_bfloat16 Bs[2][32][136];

    const int b  = blockIdx.z;
    const int o0 = blockIdx.y * 128;
    const int n0 = blockIdx.x * 128;
    const __nv_bfloat16* Mb = g_Mq + (size_t)b * CDIM * CDIM;
    const __nv_bfloat16* Qb = g_xb + (size_t)b * CDIM * NPix;
    const float* Xb = X + (size_t)b * CDIM * NPix;
    float*       Yb = Y + (size_t)b * CDIM * NPix;

    const int tid  = threadIdx.x;
    const int lane = tid & 31;
    const int wid  = tid >> 5;
    const int wm0  = (wid & 3) * 32;
    const int wn0  = (wid >> 2) * 64;

    const int aR0 = tid >> 2,          aC0 = (tid & 3) * 8;
    const int aR1 = (tid + 256) >> 2,  aC1 = ((tid + 256) & 3) * 8;
    const int bR0 = tid >> 4,          bC0 = (tid & 15) * 8;
    const int bR1 = (tid + 256) >> 4,  bC1 = ((tid + 256) & 15) * 8;
    const __nv_bfloat16* aS0 = &Mb[(size_t)(o0 + aR0) * CDIM + aC0];
    const __nv_bfloat16* aS1 = &Mb[(size_t)(o0 + aR1) * CDIM + aC1];
    const __nv_bfloat16* bS0 = &Qb[(size_t)bR0 * NPix + n0 + bC0];
    const __nv_bfloat16* bS1 = &Qb[(size_t)bR1 * NPix + n0 + bC1];

    auto stage = [&](int buf, int c0) {
        cp16(cvta_s(&As[buf][aR0][aC0]), aS0 + c0);
        cp16(cvta_s(&As[buf][aR1][aC1]), aS1 + c0);
        cp16(cvta_s(&Bs[buf][bR0][bC0]), bS0 + (size_t)c0 * NPix);
        cp16(cvta_s(&Bs[buf][bR1][bC1]), bS1 + (size_t)c0 * NPix);
    };

    float acc[2][8][4] = {};

    stage(0, 0);
    CP_COMMIT();

    #pragma unroll
    for (int it = 0; it < 8; it++) {
        const int buf = it & 1;
        CP_WAIT(0);
        __syncthreads();
        if (it < 7) { stage(buf ^ 1, (it + 1) * 32); CP_COMMIT(); }

        #pragma unroll
        for (int kk = 0; kk < 32; kk += 16) {
            uint32_t a[2][4];
            #pragma unroll
            for (int mi = 0; mi < 2; mi++) {
                uint32_t ad = cvta_s(&As[buf][wm0 + mi * 16 + (lane & 15)][kk + (lane >> 4) * 8]);
                LDSM_X4(a[mi][0], a[mi][1], a[mi][2], a[mi][3], ad);
            }
            uint32_t bfr[8][2];
            #pragma unroll
            for (int np = 0; np < 4; np++) {
                uint32_t ad = cvta_s(&Bs[buf][kk + ((lane >> 3) & 1) * 8 + (lane & 7)]
                                            [wn0 + np * 16 + (lane >> 4) * 8]);
                uint32_t r0, r1, r2, r3;
                LDSM_X4_T(r0, r1, r2, r3, ad);
                bfr[2*np][0] = r0; bfr[2*np][1] = r1;
                bfr[2*np+1][0] = r2; bfr[2*np+1][1] = r3;
            }
            #pragma unroll
            for (int mi = 0; mi < 2; mi++)
                #pragma unroll
                for (int ni = 0; ni < 8; ni++)
                    MMA_BF16(acc[mi][ni], a[mi], bfr[ni][0], bfr[ni][1]);
        }
    }

    #pragma unroll
    for (int mi = 0; mi < 2; mi++) {
        int r0 = o0 + wm0 + mi * 16 + (lane >> 2);
        int r1 = r0 + 8;
        float bias0 = gamma[r0] * b_out[r0];
        float bias1 = gamma[r1] * b_out[r1];
        #pragma unroll
        for (int ni = 0; ni < 8; ni++) {
            int cc = n0 + wn0 + ni * 8 + (lane & 3) * 2;
            size_t off0 = (size_t)r0 * NPix + cc;
            size_t off1 = (size_t)r1 * NPix + cc;
            float2 x0 = *(const float2*)&Xb[off0];
            float2 x1 = *(const float2*)&Xb[off1];
            float2 y0 = make_float2(acc[mi][ni][0] + bias0 + x0.x,
                                    acc[mi][ni][1] + bias0 + x0.y);
            float2 y1 = make_float2(acc[mi][ni][2] + bias1 + x1.x,
                                    acc[mi][ni][3] + bias1 + x1.y);
            *(float2*)&Yb[off0] = y0;
            *(float2*)&Yb[off1] = y1;
        }
    }
}

// ---------------------------------------------------------------------------
extern "C" void kernel_launch(void* const* d_in, const int* in_sizes, int n_in,
                              void* d_out, int out_size) {
    const float* x      = (const float*)d_in[0];
    const float* w_qkv  = (const float*)d_in[1];
    const float* w_out  = (const float*)d_in[2];
    const float* b_out  = (const float*)d_in[3];
    const float* gamma  = (const float*)d_in[4];
    float* y = (float*)d_out;

    k_cvt_x<<<(BATCH * CDIM * NPix) / 1024, 256>>>(x);
    k_cvt_w<<<(O3 * CDIM) / 1024, 256>>>(w_qkv);
    k_qkv<<<dim3(NPix / 128, (O3 - CDIM) / 128, BATCH), 256>>>();
    k_ctx<<<dim3(NSPLIT, BATCH * HEADS), 256>>>();
    k_mix<<<dim3(BATCH * HEADS, 4), 256>>>(w_out, gamma);
    k_mq<<<dim3(CDIM / 64, CDIM / 128, BATCH), 256>>>();
    k_out<<<dim3(NPix / 128, CDIM / 128, BATCH), 256>>>(x, b_out, gamma, y);
}

// round 12
// speedup vs baseline: 1.0870x; 1.0870x over previous
#include <cuda_runtime.h>
#include <cuda_bf16.h>
#include <cstdint>

// Problem constants
#define BATCH 16
#define CDIM  256
#define NPix  4096
#define HEADS 4
#define DH    64
#define O3    768
#define NSPLIT 16

// Scratch (__device__ globals: allocation-free rule)
__device__ __nv_bfloat16 g_qkv[(size_t)BATCH * O3 * NPix];     // K,V live in rows [256,768)
__device__ __nv_bfloat16 g_xb [(size_t)BATCH * CDIM * NPix];   // 33 MB
__device__ __nv_bfloat16 g_wq [(size_t)O3 * CDIM];             // 384 KB
__device__ float g_ctxp[(size_t)NSPLIT * BATCH * HEADS * DH * DH]; // 16 MB
__device__ float g_zp  [(size_t)NSPLIT * BATCH * HEADS * DH];      // 256 KB
__device__ __nv_bfloat16 g_M [(size_t)BATCH * CDIM * CDIM];    // 2 MB
__device__ __nv_bfloat16 g_Mq[(size_t)BATCH * CDIM * CDIM];    // 2 MB  (M @ W_q)

__device__ __forceinline__ uint32_t cvta_s(const void* p) {
    return (uint32_t)__cvta_generic_to_shared(p);
}
__device__ __forceinline__ void cp16(uint32_t dst, const void* src) {
    asm volatile("cp.async.cg.shared.global [%0], [%1], 16;" :: "r"(dst), "l"(src));
}
#define CP_COMMIT() asm volatile("cp.async.commit_group;")
#define CP_WAIT(n)  asm volatile("cp.async.wait_group %0;" :: "n"(n))

#define LDSM_X4(r0,r1,r2,r3,addr) \
    asm volatile("ldmatrix.sync.aligned.m8n8.x4.shared.b16 {%0,%1,%2,%3}, [%4];" \
                 : "=r"(r0),"=r"(r1),"=r"(r2),"=r"(r3) : "r"(addr))
#define LDSM_X4_T(r0,r1,r2,r3,addr) \
    asm volatile("ldmatrix.sync.aligned.m8n8.x4.trans.shared.b16 {%0,%1,%2,%3}, [%4];" \
                 : "=r"(r0),"=r"(r1),"=r"(r2),"=r"(r3) : "r"(addr))
#define MMA_BF16(c,a,b0,b1) \
    asm volatile("mma.sync.aligned.m16n8k16.row.col.f32.bf16.bf16.f32 " \
                 "{%0,%1,%2,%3},{%4,%5,%6,%7},{%8,%9},{%0,%1,%2,%3};" \
                 : "+f"((c)[0]),"+f"((c)[1]),"+f"((c)[2]),"+f"((c)[3]) \
                 : "r"((a)[0]),"r"((a)[1]),"r"((a)[2]),"r"((a)[3]),"r"(b0),"r"(b1))

// ---------------------------------------------------------------------------
// Conversion kernels (fp32 -> bf16)
// ---------------------------------------------------------------------------
__global__ __launch_bounds__(256) void k_cvt_x(const float* __restrict__ x) {
    size_t i = ((size_t)blockIdx.x * 256 + threadIdx.x) * 4;
    float4 v = *(const float4*)&x[i];
    __nv_bfloat162 lo, hi;
    lo.x = __float2bfloat16_rn(v.x); lo.y = __float2bfloat16_rn(v.y);
    hi.x = __float2bfloat16_rn(v.z); hi.y = __float2bfloat16_rn(v.w);
    *(__nv_bfloat162*)&g_xb[i]     = lo;
    *(__nv_bfloat162*)&g_xb[i + 2] = hi;
}
__global__ __launch_bounds__(256) void k_cvt_w(const float* __restrict__ w) {
    size_t i = ((size_t)blockIdx.x * 256 + threadIdx.x) * 4;
    float4 v = *(const float4*)&w[i];
    __nv_bfloat162 lo, hi;
    lo.x = __float2bfloat16_rn(v.x); lo.y = __float2bfloat16_rn(v.y);
    hi.x = __float2bfloat16_rn(v.z); hi.y = __float2bfloat16_rn(v.w);
    *(__nv_bfloat162*)&g_wq[i]     = lo;
    *(__nv_bfloat162*)&g_wq[i + 2] = hi;
}

// ---------------------------------------------------------------------------
// Kernel 1: K,V only. qkv[b,o,n] = sum_c W[o,c]*x[b,c,n], o in [256,768)
// bf16 HMMA, 128x128x32 tiles, cp.async 3-stage pipeline, 1 sync/iter
// ---------------------------------------------------------------------------
__global__ __launch_bounds__(256, 2) void k_qkv() {
    __shared__ __nv_bfloat16 As[3][128][40];    // [o][c]
    __shared__ __nv_bfloat16 Bs[3][32][136];    // [c][n]

    const int b  = blockIdx.z;
    const int o0 = CDIM + blockIdx.y * 128;     // skip Q rows
    const int n0 = blockIdx.x * 128;
    const __nv_bfloat16* Xb = g_xb + (size_t)b * CDIM * NPix;
    __nv_bfloat16*       Cb = g_qkv + (size_t)b * O3 * NPix;

    const int tid  = threadIdx.x;
    const int lane = tid & 31;
    const int wid  = tid >> 5;
    const int wm0  = (wid & 3) * 32;
    const int wn0  = (wid >> 2) * 64;

    const int aR0 = tid >> 2,          aC0 = (tid & 3) * 8;
    const int aR1 = (tid + 256) >> 2,  aC1 = ((tid + 256) & 3) * 8;
    const int bR0 = tid >> 4,          bC0 = (tid & 15) * 8;
    const int bR1 = (tid + 256) >> 4,  bC1 = ((tid + 256) & 15) * 8;
    const __nv_bfloat16* aS0 = &g_wq[(size_t)(o0 + aR0) * CDIM + aC0];
    const __nv_bfloat16* aS1 = &g_wq[(size_t)(o0 + aR1) * CDIM + aC1];
    const __nv_bfloat16* bS0 = &Xb[(size_t)bR0 * NPix + n0 + bC0];
    const __nv_bfloat16* bS1 = &Xb[(size_t)bR1 * NPix + n0 + bC1];

    auto stage = [&](int buf, int c0) {
        cp16(cvta_s(&As[buf][aR0][aC0]), aS0 + c0);
        cp16(cvta_s(&As[buf][aR1][aC1]), aS1 + c0);
        cp16(cvta_s(&Bs[buf][bR0][bC0]), bS0 + (size_t)c0 * NPix);
        cp16(cvta_s(&Bs[buf][bR1][bC1]), bS1 + (size_t)c0 * NPix);
    };

    float acc[2][8][4] = {};

    stage(0, 0);  CP_COMMIT();
    stage(1, 32); CP_COMMIT();

    #pragma unroll
    for (int it = 0; it < 8; it++) {          // CDIM/32 = 8 k-steps
        const int buf = it % 3;
        if (it < 7) { CP_WAIT(1); } else { CP_WAIT(0); }
        __syncthreads();      // all warps done reading buf (it-1)%3 == (it+2)%3
        if (it < 6) { stage((it + 2) % 3, (it + 2) * 32); CP_COMMIT(); }

        #pragma unroll
        for (int kk = 0; kk < 32; kk += 16) {
            uint32_t a[2][4];
            #pragma unroll
            for (int mi = 0; mi < 2; mi++) {
                uint32_t ad = cvta_s(&As[buf][wm0 + mi * 16 + (lane & 15)][kk + (lane >> 4) * 8]);
                LDSM_X4(a[mi][0], a[mi][1], a[mi][2], a[mi][3], ad);
            }
            uint32_t bfr[8][2];
            #pragma unroll
            for (int np = 0; np < 4; np++) {
                uint32_t ad = cvta_s(&Bs[buf][kk + ((lane >> 3) & 1) * 8 + (lane & 7)]
                                            [wn0 + np * 16 + (lane >> 4) * 8]);
                uint32_t r0, r1, r2, r3;
                LDSM_X4_T(r0, r1, r2, r3, ad);
                bfr[2*np][0] = r0; bfr[2*np][1] = r1;
                bfr[2*np+1][0] = r2; bfr[2*np+1][1] = r3;
            }
            #pragma unroll
            for (int mi = 0; mi < 2; mi++)
                #pragma unroll
                for (int ni = 0; ni < 8; ni++)
                    MMA_BF16(acc[mi][ni], a[mi], bfr[ni][0], bfr[ni][1]);
        }
    }

    #pragma unroll
    for (int mi = 0; mi < 2; mi++) {
        int r0 = o0 + wm0 + mi * 16 + (lane >> 2);
        #pragma unroll
        for (int ni = 0; ni < 8; ni++) {
            int cc = n0 + wn0 + ni * 8 + (lane & 3) * 2;
            __nv_bfloat162 v0, v1;
            v0.x = __float2bfloat16_rn(acc[mi][ni][0]);
            v0.y = __float2bfloat16_rn(acc[mi][ni][1]);
            v1.x = __float2bfloat16_rn(acc[mi][ni][2]);
            v1.y = __float2bfloat16_rn(acc[mi][ni][3]);
            *(__nv_bfloat162*)&Cb[(size_t)r0 * NPix + cc]       = v0;
            *(__nv_bfloat162*)&Cb[(size_t)(r0 + 8) * NPix + cc] = v1;
        }
    }
}

// ---------------------------------------------------------------------------
// Kernel 2: partial unnormalized context + partial Z.
//   ctxp[s][bh][d][e] = sum_{n in split} exp(k[d,n]) * v[e,n]
//   zp[s][bh][d]      = sum_{n in split} exp(k[d,n])
// NSPLIT=16 (256 n per block, 4 chunks of 64). K: register LDG + exp.
// V: cp.async. Double-buffered smem, 1 sync/iter.
// ---------------------------------------------------------------------------
__global__ __launch_bounds__(256) void k_ctx() {
    const int split = blockIdx.x;
    const int bh = blockIdx.y;
    const int b = bh >> 2;
    const int h = bh & 3;
    const __nv_bfloat16* kp = g_qkv + (size_t)b * O3 * NPix + (size_t)(CDIM + h * DH) * NPix;
    const __nv_bfloat16* vp = g_qkv + (size_t)b * O3 * NPix + (size_t)(2 * CDIM + h * DH) * NPix;

    __shared__ __nv_bfloat16 Ks[2][64][72];
    __shared__ __nv_bfloat16 Vs[2][64][72];

    const int tid  = threadIdx.x;
    const int lane = tid & 31;
    const int wid  = tid >> 5;
    const int wm0  = (wid & 3) * 16;   // d
    const int wn0  = (wid >> 2) * 32;  // e

    const int srow = tid >> 2;         // staging row, 0..63
    const int scol = (tid & 3) * 16;   // staging col base (16 bf16 per thread)

    const __nv_bfloat16* kSrc = &kp[(size_t)srow * NPix + scol];
    const __nv_bfloat16* vSrc = &vp[(size_t)srow * NPix + scol];

    float acc[4][4] = {};
    float zacc = 0.f;
    const int nbeg = split * (NPix / NSPLIT);   // 256-wide slice

    // Prologue: K regs + V cp.async for chunk 0
    uint4 kr0 = *(const uint4*)(kSrc + nbeg);
    uint4 kr1 = *(const uint4*)(kSrc + nbeg + 8);
    cp16(cvta_s(&Vs[0][srow][scol]),     vSrc + nbeg);
    cp16(cvta_s(&Vs[0][srow][scol + 8]), vSrc + nbeg + 8);
    CP_COMMIT();

    #pragma unroll
    for (int it = 0; it < 4; it++) {        // 256/64 = 4 chunks per split
        const int buf = it & 1;
        {   // exp(K) -> smem
            __nv_bfloat162 ko[8];
            const __nv_bfloat162* ka = (const __nv_bfloat162*)&kr0;
            const __nv_bfloat162* kb = (const __nv_bfloat162*)&kr1;
            #pragma unroll
            for (int j = 0; j < 4; j++) {
                float2 f = __bfloat1622float2(ka[j]);
                float e0 = __expf(f.x), e1 = __expf(f.y);
                zacc += e0 + e1;
                ko[j].x = __float2bfloat16_rn(e0);
                ko[j].y = __float2bfloat16_rn(e1);
            }
            #pragma unroll
            for (int j = 0; j < 4; j++) {
                float2 f = __bfloat1622float2(kb[j]);
                float e0 = __expf(f.x), e1 = __expf(f.y);
                zacc += e0 + e1;
                ko[4 + j].x = __float2bfloat16_rn(e0);
                ko[4 + j].y = __float2bfloat16_rn(e1);
            }
            *(uint4*)&Ks[buf][srow][scol]     = *(uint4*)&ko[0];
            *(uint4*)&Ks[buf][srow][scol + 8] = *(uint4*)&ko[4];
        }
        CP_WAIT(0);
        __syncthreads();   // covers V arrival + K STS visibility + prior MMA reads

        if (it < 3) {       // prefetch next chunk; latency hides under MMA
            const int nn = nbeg + (it + 1) * 64;
            kr0 = *(const uint4*)(kSrc + nn);
            kr1 = *(const uint4*)(kSrc + nn + 8);
            cp16(cvta_s(&Vs[buf ^ 1][srow][scol]),     vSrc + nn);
            cp16(cvta_s(&Vs[buf ^ 1][srow][scol + 8]), vSrc + nn + 8);
            CP_COMMIT();
        }

        #pragma unroll
        for (int kk = 0; kk < 64; kk += 16) {
            uint32_t a[4];
            {
                uint32_t ad = cvta_s(&Ks[buf][wm0 + (lane & 15)][kk + (lane >> 4) * 8]);
                LDSM_X4(a[0], a[1], a[2], a[3], ad);
            }
            uint32_t bfr[4][2];
            #pragma unroll
            for (int np = 0; np < 2; np++) {
                int g = lane >> 3, rr = lane & 7;
                uint32_t ad = cvta_s(&Vs[buf][wn0 + np * 16 + (g >> 1) * 8 + rr][kk + (g & 1) * 8]);
                uint32_t r0, r1, r2, r3;
                LDSM_X4(r0, r1, r2, r3, ad);
                bfr[2*np][0] = r0; bfr[2*np][1] = r1;
                bfr[2*np+1][0] = r2; bfr[2*np+1][1] = r3;
            }
            #pragma unroll
            for (int ni = 0; ni < 4; ni++)
                MMA_BF16(acc[ni], a, bfr[ni][0], bfr[ni][1]);
        }
    }

    // Reduce partial Z across the 4 staging threads of each row (same warp quad)
    zacc += __shfl_xor_sync(0xffffffffu, zacc, 1);
    zacc += __shfl_xor_sync(0xffffffffu, zacc, 2);
    if ((tid & 3) == 0)
        g_zp[((size_t)split * (BATCH * HEADS) + bh) * DH + srow] = zacc;

    float* cp = g_ctxp + ((size_t)split * (BATCH * HEADS) + bh) * (DH * DH);
    #pragma unroll
    for (int ni = 0; ni < 4; ni++) {
        int d = wm0 + (lane >> 2);
        int e = wn0 + ni * 8 + (lane & 3) * 2;
        *(float2*)&cp[(size_t)d * DH + e]       = make_float2(acc[ni][0], acc[ni][1]);
        *(float2*)&cp[(size_t)(d + 8) * DH + e] = make_float2(acc[ni][2], acc[ni][3]);
    }
}

// ---------------------------------------------------------------------------
// Kernel 3: M[b][o][h*64+d] = gamma[o]/Z_d * sum_e w_out[o][h*64+e]*ctx[b,h][d][e]
// ---------------------------------------------------------------------------
__global__ __launch_bounds__(256) void k_mix(const float* __restrict__ Wout,
                                             const float* __restrict__ gamma) {
    const int bh = blockIdx.x;
    const int og = blockIdx.y;
    const int b = bh >> 2;
    const int h = bh & 3;

    __shared__ float cs[64][65];
    __shared__ float zs[64];
    const int tid = threadIdx.x;

    if (tid < 64) {
        float s = 0.f;
        #pragma unroll
        for (int sp = 0; sp < NSPLIT; sp++)
            s += g_zp[((size_t)sp * (BATCH * HEADS) + bh) * DH + tid];
        zs[tid] = 1.0f / s;
    }
    __syncthreads();

    for (int idx = tid; idx < DH * DH; idx += 256) {
        float s = 0.f;
        #pragma unroll
        for (int sp = 0; sp < NSPLIT; sp++)
            s += g_ctxp[((size_t)sp * (BATCH * HEADS) + bh) * (DH * DH) + idx];
        cs[idx >> 6][idx & 63] = s * zs[idx >> 6];
    }
    __syncthreads();

    const int o  = og * 64 + (tid >> 2);
    const int d0 = (tid & 3) * 16;

    float acc[16];
    #pragma unroll
    for (int j = 0; j < 16; j++) acc[j] = 0.f;

    for (int e = 0; e < 64; e++) {
        const float w = Wout[(size_t)o * CDIM + h * DH + e];
        #pragma unroll
        for (int j = 0; j < 16; j++)
            acc[j] = fmaf(w, cs[d0 + j][e], acc[j]);
    }
    const float g = gamma[o];
    __nv_bfloat16* mp = g_M + ((size_t)b * CDIM + o) * CDIM + h * DH + d0;
    #pragma unroll
    for (int j = 0; j < 16; j++) mp[j] = __float2bfloat16_rn(g * acc[j]);
}

// ---------------------------------------------------------------------------
// Kernel 4: Mq[b] = M[b] @ Wq   (Wq = w_qkv rows [0,256), bf16 in g_wq)
// 128x64 tiles, K=256, cp.async double-buffered. (tiny: 64 blocks, ~3us)
// ---------------------------------------------------------------------------
__global__ __launch_bounds__(256, 2) void k_mq() {
    __shared__ __nv_bfloat16 As[2][128][40];   // [o][c']
    __shared__ __nv_bfloat16 Bs[2][32][72];    // [c'][c]

    const int b  = blockIdx.z;
    const int o0 = blockIdx.y * 128;
    const int n0 = blockIdx.x * 64;
    const __nv_bfloat16* Ma = g_M  + (size_t)b * CDIM * CDIM;
    __nv_bfloat16*       Cb = g_Mq + (size_t)b * CDIM * CDIM;

    const int tid  = threadIdx.x;
    const int lane = tid & 31;
    const int wid  = tid >> 5;
    const int wm0  = (wid & 3) * 32;
    const int wn0  = (wid >> 2) * 32;

    const int aR0 = tid >> 2,          aC0 = (tid & 3) * 8;
    const int aR1 = (tid + 256) >> 2,  aC1 = ((tid + 256) & 3) * 8;
    const int bR  = tid >> 3,          bC  = (tid & 7) * 8;
    const __nv_bfloat16* aS0 = &Ma[(size_t)(o0 + aR0) * CDIM + aC0];
    const __nv_bfloat16* aS1 = &Ma[(size_t)(o0 + aR1) * CDIM + aC1];
    const __nv_bfloat16* bS  = &g_wq[(size_t)bR * CDIM + n0 + bC];

    auto stage = [&](int buf, int c0) {
        cp16(cvta_s(&As[buf][aR0][aC0]), aS0 + c0);
        cp16(cvta_s(&As[buf][aR1][aC1]), aS1 + c0);
        cp16(cvta_s(&Bs[buf][bR][bC]),   bS + (size_t)c0 * CDIM);
    };

    float acc[2][4][4] = {};

    stage(0, 0);
    CP_COMMIT();

    #pragma unroll
    for (int it = 0; it < 8; it++) {
        const int buf = it & 1;
        if (it < 7) { stage(buf ^ 1, (it + 1) * 32); CP_COMMIT(); }
        if (it < 7) { CP_WAIT(1); } else { CP_WAIT(0); }
        __syncthreads();

        #pragma unroll
        for (int kk = 0; kk < 32; kk += 16) {
            uint32_t a[2][4];
            #pragma unroll
            for (int mi = 0; mi < 2; mi++) {
                uint32_t ad = cvta_s(&As[buf][wm0 + mi * 16 + (lane & 15)][kk + (lane >> 4) * 8]);
                LDSM_X4(a[mi][0], a[mi][1], a[mi][2], a[mi][3], ad);
            }
            uint32_t bfr[4][2];
            #pragma unroll
            for (int np = 0; np < 2; np++) {
                uint32_t ad = cvta_s(&Bs[buf][kk + ((lane >> 3) & 1) * 8 + (lane & 7)]
                                            [wn0 + np * 16 + (lane >> 4) * 8]);
                uint32_t r0, r1, r2, r3;
                LDSM_X4_T(r0, r1, r2, r3, ad);
                bfr[2*np][0] = r0; bfr[2*np][1] = r1;
                bfr[2*np+1][0] = r2; bfr[2*np+1][1] = r3;
            }
            #pragma unroll
            for (int mi = 0; mi < 2; mi++)
                #pragma unroll
                for (int ni = 0; ni < 4; ni++)
                    MMA_BF16(acc[mi][ni], a[mi], bfr[ni][0], bfr[ni][1]);
        }
        __syncthreads();
    }

    #pragma unroll
    for (int mi = 0; mi < 2; mi++) {
        int r0 = o0 + wm0 + mi * 16 + (lane >> 2);
        #pragma unroll
        for (int ni = 0; ni < 4; ni++) {
            int cc = n0 + wn0 + ni * 8 + (lane & 3) * 2;
            __nv_bfloat162 v0, v1;
            v0.x = __float2bfloat16_rn(acc[mi][ni][0]);
            v0.y = __float2bfloat16_rn(acc[mi][ni][1]);
            v1.x = __float2bfloat16_rn(acc[mi][ni][2]);
            v1.y = __float2bfloat16_rn(acc[mi][ni][3]);
            *(__nv_bfloat162*)&Cb[(size_t)r0 * CDIM + cc]       = v0;
            *(__nv_bfloat162*)&Cb[(size_t)(r0 + 8) * CDIM + cc] = v1;
        }
    }
}

// ---------------------------------------------------------------------------
// Kernel 5: y[b,o,n] = sum_c Mq[b][o][c]*xb[b,c,n] + gamma[o]*b_out[o] + x[b,o,n]
// bf16 HMMA, cp.async 3-stage pipeline, 1 sync/iter, fused fp32 epilogue
// ---------------------------------------------------------------------------
__global__ __launch_bounds__(256, 2) void k_out(const float* __restrict__ X,
                                                const float* __restrict__ b_out,
                                                const float* __restrict__ gamma,
                                                float* __restrict__ Y) {
    __shared__ __nv_bfloat16 As[3][128][40];
    __shared__ __nv_bfloat16 Bs[3][32][136];

    const int b  = blockIdx.z;
    const int o0 = blockIdx.y * 128;
    const int n0 = blockIdx.x * 128;
    const __nv_bfloat16* Mb = g_Mq + (size_t)b * CDIM * CDIM;
    const __nv_bfloat16* Qb = g_xb + (size_t)b * CDIM * NPix;
    const float* Xb = X + (size_t)b * CDIM * NPix;
    float*       Yb = Y + (size_t)b * CDIM * NPix;

    const int tid  = threadIdx.x;
    const int lane = tid & 31;
    const int wid  = tid >> 5;
    const int wm0  = (wid & 3) * 32;
    const int wn0  = (wid >> 2) * 64;

    const int aR0 = tid >> 2,          aC0 = (tid & 3) * 8;
    const int aR1 = (tid + 256) >> 2,  aC1 = ((tid + 256) & 3) * 8;
    const int bR0 = tid >> 4,          bC0 = (tid & 15) * 8;
    const int bR1 = (tid + 256) >> 4,  bC1 = ((tid + 256) & 15) * 8;
    const __nv_bfloat16* aS0 = &Mb[(size_t)(o0 + aR0) * CDIM + aC0];
    const __nv_bfloat16* aS1 = &Mb[(size_t)(o0 + aR1) * CDIM + aC1];
    const __nv_bfloat16* bS0 = &Qb[(size_t)bR0 * NPix + n0 + bC0];
    const __nv_bfloat16* bS1 = &Qb[(size_t)bR1 * NPix + n0 + bC1];

    auto stage = [&](int buf, int c0) {
        cp16(cvta_s(&As[buf][aR0][aC0]), aS0 + c0);
        cp16(cvta_s(&As[buf][aR1][aC1]), aS1 + c0);
        cp16(cvta_s(&Bs[buf][bR0][bC0]), bS0 + (size_t)c0 * NPix);
        cp16(cvta_s(&Bs[buf][bR1][bC1]), bS1 + (size_t)c0 * NPix);
    };

    float acc[2][8][4] = {};

    stage(0, 0);  CP_COMMIT();
    stage(1, 32); CP_COMMIT();

    #pragma unroll
    for (int it = 0; it < 8; it++) {
        const int buf = it % 3;
        if (it < 7) { CP_WAIT(1); } else { CP_WAIT(0); }
        __syncthreads();
        if (it < 6) { stage((it + 2) % 3, (it + 2) * 32); CP_COMMIT(); }

        #pragma unroll
        for (int kk = 0; kk < 32; kk += 16) {
            uint32_t a[2][4];
            #pragma unroll
            for (int mi = 0; mi < 2; mi++) {
                uint32_t ad = cvta_s(&As[buf][wm0 + mi * 16 + (lane & 15)][kk + (lane >> 4) * 8]);
                LDSM_X4(a[mi][0], a[mi][1], a[mi][2], a[mi][3], ad);
            }
            uint32_t bfr[8][2];
            #pragma unroll
            for (int np = 0; np < 4; np++) {
                uint32_t ad = cvta_s(&Bs[buf][kk + ((lane >> 3) & 1) * 8 + (lane & 7)]
                                            [wn0 + np * 16 + (lane >> 4) * 8]);
                uint32_t r0, r1, r2, r3;
                LDSM_X4_T(r0, r1, r2, r3, ad);
                bfr[2*np][0] = r0; bfr[2*np][1] = r1;
                bfr[2*np+1][0] = r2; bfr[2*np+1][1] = r3;
            }
            #pragma unroll
            for (int mi = 0; mi < 2; mi++)
                #pragma unroll
                for (int ni = 0; ni < 8; ni++)
                    MMA_BF16(acc[mi][ni], a[mi], bfr[ni][0], bfr[ni][1]);
        }
    }

    #pragma unroll
    for (int mi = 0; mi < 2; mi++) {
        int r0 = o0 + wm0 + mi * 16 + (lane >> 2);
        int r1 = r0 + 8;
        float bias0 = gamma[r0] * b_out[r0];
        float bias1 = gamma[r1] * b_out[r1];
        #pragma unroll
        for (int ni = 0; ni < 8; ni++) {
            int cc = n0 + wn0 + ni * 8 + (lane & 3) * 2;
            size_t off0 = (size_t)r0 * NPix + cc;
            size_t off1 = (size_t)r1 * NPix + cc;
            float2 x0 = *(const float2*)&Xb[off0];
            float2 x1 = *(const float2*)&Xb[off1];
            float2 y0 = make_float2(acc[mi][ni][0] + bias0 + x0.x,
                                    acc[mi][ni][1] + bias0 + x0.y);
            float2 y1 = make_float2(acc[mi][ni][2] + bias1 + x1.x,
                                    acc[mi][ni][3] + bias1 + x1.y);
            *(float2*)&Yb[off0] = y0;
            *(float2*)&Yb[off1] = y1;
        }
    }
}

// ---------------------------------------------------------------------------
extern "C" void kernel_launch(void* const* d_in, const int* in_sizes, int n_in,
                              void* d_out, int out_size) {
    const float* x      = (const float*)d_in[0];
    const float* w_qkv  = (const float*)d_in[1];
    const float* w_out  = (const float*)d_in[2];
    const float* b_out  = (const float*)d_in[3];
    const float* gamma  = (const float*)d_in[4];
    float* y = (float*)d_out;

    k_cvt_x<<<(BATCH * CDIM * NPix) / 1024, 256>>>(x);
    k_cvt_w<<<(O3 * CDIM) / 1024, 256>>>(w_qkv);
    k_qkv<<<dim3(NPix / 128, (O3 - CDIM) / 128, BATCH), 256>>>();
    k_ctx<<<dim3(NSPLIT, BATCH * HEADS), 256>>>();
    k_mix<<<dim3(BATCH * HEADS, 4), 256>>>(w_out, gamma);
    k_mq<<<dim3(CDIM / 64, CDIM / 128, BATCH), 256>>>();
    k_out<<<dim3(NPix / 128, CDIM / 128, BATCH), 256>>>(x, b_out, gamma, y);
}